// round 2
// baseline (speedup 1.0000x reference)
#include <cuda_runtime.h>
#include <math.h>

namespace {

constexpr int T   = 512;
constexpr int D   = 512;
constexpr int Bb  = 16;
constexpr int DT  = 16;          // d-tile per CTA
constexpr int NTH = 256;
constexpr int NTILES = D / DT;   // 32
constexpr int F   = 255;         // freq bins 1..255
constexpr float TWO_PI = 6.2831853071795864769f;

struct Smem {
    float  xs[T * DT];            // x, then x_rem (in place)
    float  cs[(T + 1) * DT];      // prefix sums of x_rem
    float  scratch[T * DT];       // phase1: Re/Im (255*16 float2); phase2+: season
    float2 tab[T];                // (cos, sin)(2*pi*j/512)
    float  wl[T];                 // W_lin
    float  wt[8], bt[8];          // W_trend, b_trend (6 used)
    int    selk[DT][4];           // selected freq index k (1..255)
    float  selRe[DT][4];
    float  selIm[DT][4];
    float  xr0[DT], xrL[DT];      // x_rem at t=0 and t=T-1 (edge replication)
    float  red[NTH];
};

__device__ float g_xtrans[Bb * D];

} // namespace

__global__ __launch_bounds__(NTH) void msr_main(
    const float* __restrict__ x,
    const float* __restrict__ wt_g,
    const float* __restrict__ bt_g,
    const float* __restrict__ wl_g,
    const float* __restrict__ bl_g)
{
    extern __shared__ unsigned char smem_raw[];
    Smem& sm = *reinterpret_cast<Smem*>(smem_raw);

    const int tid = threadIdx.x;
    const int b   = blockIdx.y;
    const int d0  = blockIdx.x * DT;

    // ---- init tables ----
    for (int j = tid; j < T; j += NTH) {
        float s, c;
        sincosf(TWO_PI * (float)j / (float)T, &s, &c);
        sm.tab[j] = make_float2(c, s);
        sm.wl[j]  = wl_g[j];
    }
    if (tid < 6) { sm.wt[tid] = wt_g[tid]; sm.bt[tid] = bt_g[tid]; }

    // ---- load x tile: xs[t*DT + dd] = x[b, t, d0+dd] ----
    {
        const float* xb = x + (size_t)b * T * D + d0;
        const int q = (tid & 3) * 4;
        const int t0 = tid >> 2;
        #pragma unroll
        for (int i = 0; i < 8; i++) {
            int t = t0 + 64 * i;
            float4 v = *reinterpret_cast<const float4*>(xb + (size_t)t * D + q);
            *reinterpret_cast<float4*>(&sm.xs[t * DT + q]) = v;
        }
    }
    __syncthreads();

    // ---- Phase 1: direct DFT, thread owns frequency f = tid+1 ----
    {
        const int f = tid + 1;                     // 1..256 (256 = Nyquist, discarded)
        const float2 w = sm.tab[f & (T - 1)];
        const float cw = w.x, sw = w.y;
        float cr = 1.f, si = 0.f;
        float accR[DT], accI[DT];
        #pragma unroll
        for (int dd = 0; dd < DT; dd++) { accR[dd] = 0.f; accI[dd] = 0.f; }

        for (int t = 0; t < T; t++) {
            if ((t & 63) == 0) {                   // resync twiddle from exact table
                float2 e = sm.tab[(f * t) & (T - 1)];
                cr = e.x; si = e.y;
            }
            float4 a0 = *reinterpret_cast<const float4*>(&sm.xs[t * DT + 0]);
            float4 a1 = *reinterpret_cast<const float4*>(&sm.xs[t * DT + 4]);
            float4 a2 = *reinterpret_cast<const float4*>(&sm.xs[t * DT + 8]);
            float4 a3 = *reinterpret_cast<const float4*>(&sm.xs[t * DT + 12]);
            accR[0]  = fmaf(a0.x,  cr, accR[0]);  accI[0]  = fmaf(-a0.x, si, accI[0]);
            accR[1]  = fmaf(a0.y,  cr, accR[1]);  accI[1]  = fmaf(-a0.y, si, accI[1]);
            accR[2]  = fmaf(a0.z,  cr, accR[2]);  accI[2]  = fmaf(-a0.z, si, accI[2]);
            accR[3]  = fmaf(a0.w,  cr, accR[3]);  accI[3]  = fmaf(-a0.w, si, accI[3]);
            accR[4]  = fmaf(a1.x,  cr, accR[4]);  accI[4]  = fmaf(-a1.x, si, accI[4]);
            accR[5]  = fmaf(a1.y,  cr, accR[5]);  accI[5]  = fmaf(-a1.y, si, accI[5]);
            accR[6]  = fmaf(a1.z,  cr, accR[6]);  accI[6]  = fmaf(-a1.z, si, accI[6]);
            accR[7]  = fmaf(a1.w,  cr, accR[7]);  accI[7]  = fmaf(-a1.w, si, accI[7]);
            accR[8]  = fmaf(a2.x,  cr, accR[8]);  accI[8]  = fmaf(-a2.x, si, accI[8]);
            accR[9]  = fmaf(a2.y,  cr, accR[9]);  accI[9]  = fmaf(-a2.y, si, accI[9]);
            accR[10] = fmaf(a2.z,  cr, accR[10]); accI[10] = fmaf(-a2.z, si, accI[10]);
            accR[11] = fmaf(a2.w,  cr, accR[11]); accI[11] = fmaf(-a2.w, si, accI[11]);
            accR[12] = fmaf(a3.x,  cr, accR[12]); accI[12] = fmaf(-a3.x, si, accI[12]);
            accR[13] = fmaf(a3.y,  cr, accR[13]); accI[13] = fmaf(-a3.y, si, accI[13]);
            accR[14] = fmaf(a3.z,  cr, accR[14]); accI[14] = fmaf(-a3.z, si, accI[14]);
            accR[15] = fmaf(a3.w,  cr, accR[15]); accI[15] = fmaf(-a3.w, si, accI[15]);
            float c2 = cr * cw - si * sw;
            si = fmaf(si, cw, cr * sw);
            cr = c2;
        }

        if (tid < F) {
            float2* ri = reinterpret_cast<float2*>(sm.scratch);
            #pragma unroll
            for (int dd = 0; dd < DT; dd++)
                ri[tid * DT + dd] = make_float2(accR[dd], accI[dd]);
        }
    }
    __syncthreads();

    // ---- Phase 1b: per-d top-4 |X|^2 (tie -> lower index, like lax.top_k) ----
    {
        const int lane = tid & 31, wid = tid >> 5;
        const float2* ri = reinterpret_cast<const float2*>(sm.scratch);
        for (int dd = wid * 2; dd < wid * 2 + 2; dd++) {
            int sel0 = -1, sel1 = -1, sel2 = -1, sel3 = -1;
            #pragma unroll
            for (int pass = 0; pass < 4; pass++) {
                float best = -1.f; int bi = 0x7fffffff;
                for (int r = lane; r < F; r += 32) {
                    if (r == sel0 || r == sel1 || r == sel2 || r == sel3) continue;
                    float2 v = ri[r * DT + dd];
                    float a = v.x * v.x + v.y * v.y;
                    if (a > best || (a == best && r < bi)) { best = a; bi = r; }
                }
                #pragma unroll
                for (int off = 16; off > 0; off >>= 1) {
                    float ob = __shfl_down_sync(0xffffffffu, best, off);
                    int   oi = __shfl_down_sync(0xffffffffu, bi,   off);
                    if (ob > best || (ob == best && oi < bi)) { best = ob; bi = oi; }
                }
                bi = __shfl_sync(0xffffffffu, bi, 0);
                if      (pass == 0) sel0 = bi;
                else if (pass == 1) sel1 = bi;
                else if (pass == 2) sel2 = bi;
                else                sel3 = bi;
            }
            if (lane == 0) {
                int s4[4] = { sel0, sel1, sel2, sel3 };
                #pragma unroll
                for (int j = 0; j < 4; j++) {
                    int r = s4[j];
                    float2 v = ri[r * DT + dd];
                    sm.selk[dd][j]  = r + 1;     // actual frequency index
                    sm.selRe[dd][j] = v.x;
                    sm.selIm[dd][j] = v.y;
                }
            }
        }
    }
    __syncthreads();

    // ---- Phase 2: season(t,d), x_rem = x - season (in place), store season ----
    {
        const float scale = 2.0f / (float)T;
        for (int idx = tid; idx < T * DT; idx += NTH) {
            int t = idx >> 4, dd = idx & 15;
            float se = 0.f;
            #pragma unroll
            for (int j = 0; j < 4; j++) {
                int k = sm.selk[dd][j];
                float2 e = sm.tab[(k * t) & (T - 1)];
                se = fmaf(sm.selRe[dd][j], e.x, se);
                se = fmaf(-sm.selIm[dd][j], e.y, se);
            }
            se *= scale;
            float xr = sm.xs[idx] - se;
            sm.xs[idx] = xr;
            sm.scratch[idx] = se;
            if (t == 0)     sm.xr0[dd] = xr;
            if (t == T - 1) sm.xrL[dd] = xr;
        }
    }
    __syncthreads();

    // ---- Phase 3: prefix sums of x_rem per d ----
    if (tid < DT) {
        float run = 0.f;
        sm.cs[tid] = 0.f;
        for (int t = 0; t < T; t++) {
            run += sm.xs[t * DT + tid];
            sm.cs[(t + 1) * DT + tid] = run;
        }
    }
    __syncthreads();

    // ---- Phase 4: moving averages + softmax blend + W_lin reduction ----
    {
        const int dd = tid & 15;
        const float x0 = sm.xr0[dd], xL = sm.xrL[dd];
        float wtr[6], btr[6];
        #pragma unroll
        for (int j = 0; j < 6; j++) { wtr[j] = sm.wt[j]; btr[j] = sm.bt[j]; }

        float acc = 0.f;
        const int tb = tid >> 4;
        #pragma unroll 4
        for (int i = 0; i < 32; i++) {
            int t = tb + 16 * i;
            float xr = sm.xs[t * DT + dd];
            float num = 0.f, den = 0.f;
            const int ksArr[6] = { 4, 8, 12, 16, 24, 32 };
            #pragma unroll
            for (int j = 0; j < 6; j++) {
                const int k = ksArr[j];
                const int h = k >> 1;
                int lo = t - h, hi = t + h - 1;
                int hiC = hi < (T - 1) ? hi : (T - 1);
                int loC = lo > 0 ? lo : 0;
                float s = sm.cs[(hiC + 1) * DT + dd] - sm.cs[loC * DT + dd];
                if (lo < 0)     s = fmaf((float)(-lo), x0, s);
                if (hi > T - 1) s = fmaf((float)(hi - (T - 1)), xL, s);
                float e = __expf(fmaf(xr, wtr[j], btr[j]));
                den += e;
                num = fmaf(s * (1.0f / (float)k), e, num);
            }
            float xsum = xr + 2.f * sm.scratch[t * DT + dd] + num / den;
            acc = fmaf(xsum, sm.wl[t], acc);
        }
        sm.red[tid] = acc;
    }
    __syncthreads();

    if (tid < DT) {
        float s = 0.f;
        #pragma unroll
        for (int j = 0; j < NTH / DT; j++) s += sm.red[tid + DT * j];
        g_xtrans[b * D + d0 + tid] = s + bl_g[0];
    }
}

__global__ __launch_bounds__(32) void msr_final(
    const float* __restrict__ noise,
    const float* __restrict__ Wr, const float* __restrict__ br,
    const float* __restrict__ Wn, const float* __restrict__ bn,
    float* __restrict__ out)
{
    const int b = blockIdx.x, lane = threadIdx.x;
    float aB[8], aN[8];
    #pragma unroll
    for (int m = 0; m < 8; m++) { aB[m] = 0.f; aN[m] = 0.f; }

    for (int d = lane; d < D; d += 32) {
        float xt = g_xtrans[b * D + d];
        #pragma unroll
        for (int m = 0; m < 8; m++) {
            aB[m] = fmaf(xt, Wr[d * 8 + m], aB[m]);
            aN[m] = fmaf(xt, Wn[d * 8 + m], aN[m]);
        }
    }
    #pragma unroll
    for (int m = 0; m < 8; m++) {
        #pragma unroll
        for (int off = 16; off > 0; off >>= 1) {
            aB[m] += __shfl_down_sync(0xffffffffu, aB[m], off);
            aN[m] += __shfl_down_sync(0xffffffffu, aN[m], off);
        }
    }
    if (lane == 0) {
        float pw[8];
        float mx = -1e30f;
        #pragma unroll
        for (int m = 0; m < 8; m++) {
            float z  = aN[m] + bn[m];
            float sp = (z > 20.f) ? z : log1pf(expf(z));   // softplus
            float l  = aB[m] + br[m] + noise[b * 8 + m] * sp;
            pw[m] = l;
            if (l > mx) mx = l;
        }
        float s = 0.f;
        #pragma unroll
        for (int m = 0; m < 8; m++) { pw[m] = expf(pw[m] - mx); s += pw[m]; }
        float inv = 1.f / s;
        #pragma unroll
        for (int m = 0; m < 8; m++) pw[m] *= inv;

        // top-4 of 8 (tie -> lower index); keep mask in a bitfield
        unsigned kept = 0u;
        #pragma unroll
        for (int p = 0; p < 4; p++) {
            float best = -1.f; int bi = 0;
            #pragma unroll
            for (int m = 0; m < 8; m++) {
                bool free_m = ((kept >> m) & 1u) == 0u;
                if (free_m && pw[m] > best) { best = pw[m]; bi = m; }
            }
            kept |= (1u << bi);
        }
        #pragma unroll
        for (int m = 0; m < 8; m++)
            out[b * 8 + m] = ((kept >> m) & 1u) ? pw[m] : 0.f;
    }
}

extern "C" void kernel_launch(void* const* d_in, const int* in_sizes, int n_in,
                              void* d_out, int out_size) {
    const float* x     = (const float*)d_in[0];
    const float* noise = (const float*)d_in[1];
    const float* Wr    = (const float*)d_in[2];
    const float* br    = (const float*)d_in[3];
    const float* Wn    = (const float*)d_in[4];
    const float* bn    = (const float*)d_in[5];
    const float* wt    = (const float*)d_in[6];
    const float* bt    = (const float*)d_in[7];
    const float* wl    = (const float*)d_in[8];
    const float* bl    = (const float*)d_in[9];
    float* out = (float*)d_out;

    (void)cudaFuncSetAttribute(msr_main, cudaFuncAttributeMaxDynamicSharedMemorySize,
                               (int)sizeof(Smem));
    dim3 grid(NTILES, Bb);
    msr_main<<<grid, NTH, sizeof(Smem)>>>(x, wt, bt, wl, bl);
    msr_final<<<Bb, 32>>>(noise, Wr, br, Wn, bn, out);
}